// round 4
// baseline (speedup 1.0000x reference)
#include <cuda_runtime.h>
#include <cuda_bf16.h>
#include <math.h>

#define B_ 1024
#define T_ 250
#define D_ 158
#define H_ 128
#define G_ 512          // 4*H
#define M_ (B_*T_)      // 256000 rows
#define P_ 64
#define O_ 22

typedef unsigned long long ull;

// ---------------- scratch (device globals: the sanctioned alloc-free path) ----------------
__device__ float g_xn[(size_t)M_ * D_];   // LN output; later reused as layer-1 h output
__device__ float g_xg[(size_t)M_ * G_];   // precomputed input gates for current layer
__device__ float g_h0[(size_t)M_ * H_];   // layer-0 h sequence
__device__ float g_Wt0[H_ * G_];          // W_hh0 transposed to [k][g]
__device__ float g_Wt1[H_ * G_];

// ---------------- f32x2 packed-FMA helpers ----------------
__device__ __forceinline__ void fma2(ull& d, ull a, ull b, ull c) {
    asm("fma.rn.f32x2 %0, %1, %2, %3;" : "=l"(d) : "l"(a), "l"(b), "l"(c));
}
__device__ __forceinline__ ull pack2(float a, float b) {
    ull r; asm("mov.b64 %0, {%1,%2};" : "=l"(r) : "f"(a), "f"(b)); return r;
}
__device__ __forceinline__ float2 upk2(ull v) {
    float2 r; asm("mov.b64 {%0,%1}, %2;" : "=f"(r.x), "=f"(r.y) : "l"(v)); return r;
}

// ---------------- activation helpers ----------------
__device__ __forceinline__ float sigm_(float x) {
    return 1.f / (1.f + __expf(-x));
}
__device__ __forceinline__ float tanh_fast(float x) {
    float a = fabsf(x);
    float e = __expf(a + a);
    float t = 1.f - 2.f / (e + 1.f);
    return copysignf(t, x);
}

// ---------------- W_hh transpose: W[512][128] -> Wt[128][512] ----------------
__global__ void transpose_whh_kernel(const float* __restrict__ W, float* __restrict__ Wt) {
    int idx = blockIdx.x * blockDim.x + threadIdx.x;   // 65536 total
    int g = idx >> 7;
    int k = idx & 127;
    Wt[k * G_ + g] = W[idx];
}

// ---------------- LayerNorm over last dim (158) ----------------
__global__ void __launch_bounds__(256) ln_kernel(const float* __restrict__ x,
                                                 const float* __restrict__ gamma,
                                                 const float* __restrict__ beta,
                                                 float* __restrict__ xn) {
    int row  = blockIdx.x * 8 + (threadIdx.x >> 5);
    int lane = threadIdx.x & 31;
    const float* xr = x + (size_t)row * D_;
    float v[5];
    float s = 0.f, s2 = 0.f;
#pragma unroll
    for (int i = 0; i < 5; i++) {
        int k = lane + 32 * i;
        v[i] = (k < D_) ? xr[k] : 0.f;
        s += v[i];
        s2 = fmaf(v[i], v[i], s2);
    }
#pragma unroll
    for (int o = 16; o; o >>= 1) {
        s  += __shfl_xor_sync(0xffffffffu, s, o);
        s2 += __shfl_xor_sync(0xffffffffu, s2, o);
    }
    float mu  = s * (1.f / D_);
    float var = s2 * (1.f / D_) - mu * mu;
    float inv = rsqrtf(var + 1e-5f);
    float* xo = xn + (size_t)row * D_;
#pragma unroll
    for (int i = 0; i < 5; i++) {
        int k = lane + 32 * i;
        if (k < D_) xo[k] = (v[i] - mu) * inv * gamma[k] + beta[k];
    }
}

// ---------------- FFMA2 GEMM: C[M,512] = A[M,K] * W[512,K]^T + bias ----------------
// BM=128, BN=128, BK=16, 256 threads, 8x8 microtile, A pre-duplicated for f32x2.
template <int K>
__global__ void __launch_bounds__(256, 2) gemm2_kernel(const float* __restrict__ A,
                                                       const float* __restrict__ W,
                                                       const float* __restrict__ bias,
                                                       float* __restrict__ C) {
    __shared__ ull   As[2][16][128];   // (a,a) duplicated pairs: 32 KB
    __shared__ float Bs[2][16][128];   // 16 KB
    constexpr int NT = (K + 15) / 16;

    int tid = threadIdx.x;
    int row = tid >> 1;                // 0..127
    int kb  = (tid & 1) * 8;           // 0 or 8
    int m0 = blockIdx.y * 128, n0 = blockIdx.x * 128;
    int tx = tid & 15, ty = tid >> 4;

    const float* Arow = A + (size_t)(m0 + row) * K;
    const float* Wrow = W + (size_t)(n0 + row) * K;

    ull acc[8][4];
#pragma unroll
    for (int i = 0; i < 8; i++)
#pragma unroll
        for (int j = 0; j < 4; j++) acc[i][j] = 0ull;

    float ar[8], br[8];
    // prologue: tile 0
#pragma unroll
    for (int j = 0; j < 8; j++) {
        int k = kb + j;
        ar[j] = (k < K) ? Arow[k] : 0.f;
        br[j] = (k < K) ? Wrow[k] : 0.f;
    }
#pragma unroll
    for (int j = 0; j < 8; j++) {
        As[0][kb + j][row] = pack2(ar[j], ar[j]);
        Bs[0][kb + j][row] = br[j];
    }
    __syncthreads();

    for (int tIdx = 0; tIdx < NT; tIdx++) {
        int cur = tIdx & 1, nxt = cur ^ 1;
        if (tIdx + 1 < NT) {
            int k0 = (tIdx + 1) * 16;
#pragma unroll
            for (int j = 0; j < 8; j++) {
                int k = k0 + kb + j;
                ar[j] = (k < K) ? Arow[k] : 0.f;
                br[j] = (k < K) ? Wrow[k] : 0.f;
            }
        }
#pragma unroll
        for (int kk = 0; kk < 16; kk++) {
            const longlong2* ap = (const longlong2*)&As[cur][kk][ty * 8];
            longlong2 a01 = ap[0], a23 = ap[1], a45 = ap[2], a67 = ap[3];
            const longlong2* bp = (const longlong2*)&Bs[cur][kk][tx * 8];
            longlong2 b03 = bp[0], b47 = bp[1];
            ull au[8] = {(ull)a01.x, (ull)a01.y, (ull)a23.x, (ull)a23.y,
                         (ull)a45.x, (ull)a45.y, (ull)a67.x, (ull)a67.y};
            ull bu[4] = {(ull)b03.x, (ull)b03.y, (ull)b47.x, (ull)b47.y};
#pragma unroll
            for (int i = 0; i < 8; i++)
#pragma unroll
                for (int j = 0; j < 4; j++)
                    fma2(acc[i][j], au[i], bu[j], acc[i][j]);
        }
        if (tIdx + 1 < NT) {
#pragma unroll
            for (int j = 0; j < 8; j++) {
                As[nxt][kb + j][row] = pack2(ar[j], ar[j]);
                Bs[nxt][kb + j][row] = br[j];
            }
        }
        __syncthreads();
    }

    // epilogue: add bias, store float4 pairs
    float bb[8];
#pragma unroll
    for (int j = 0; j < 8; j++) bb[j] = bias[n0 + tx * 8 + j];
#pragma unroll
    for (int i = 0; i < 8; i++) {
        float2 p0 = upk2(acc[i][0]);
        float2 p1 = upk2(acc[i][1]);
        float2 p2 = upk2(acc[i][2]);
        float2 p3 = upk2(acc[i][3]);
        float4 v0 = make_float4(p0.x + bb[0], p0.y + bb[1], p1.x + bb[2], p1.y + bb[3]);
        float4 v1 = make_float4(p2.x + bb[4], p2.y + bb[5], p3.x + bb[6], p3.y + bb[7]);
        float* crow = C + (size_t)(m0 + ty * 8 + i) * G_ + n0 + tx * 8;
        *(float4*)(crow)     = v0;
        *(float4*)(crow + 4) = v1;
    }
}

// ---------------- LSTM recurrence: one CTA owns 8 batch rows, FFMA2 inner loop ----------------
// xg: [B*T, 512] (row = b*T + t), Wt: [128][512] k-major, hout: [B*T, 128]
__global__ void __launch_bounds__(256) lstm8_kernel(const float* __restrict__ xg,
                                                    const float* __restrict__ Wt,
                                                    float* __restrict__ hout) {
    __shared__ ull   hs_dup[128][8];   // (h,h) per [k][row], 8 KB
    __shared__ float gs[8][512];       // gates per row, 16 KB
    int tid = threadIdx.x;
    int b0 = blockIdx.x * 8;

    const ull* WtP = (const ull*)Wt;   // [128][256] gate pairs

    // phase-B task mapping: 512 (row, jpair) tasks, 2 per thread
    int r_b[2], j_b[2];
    float2 c_b[2];
#pragma unroll
    for (int q = 0; q < 2; q++) {
        int task = tid + 256 * q;
        r_b[q] = task >> 6;            // 0..7
        j_b[q] = (task & 63) * 2;      // even j
        c_b[q] = make_float2(0.f, 0.f);
    }

    for (int i = tid; i < 128 * 8; i += 256) ((ull*)hs_dup)[i] = 0ull;
    __syncthreads();

    const float* xg_base[8];
#pragma unroll
    for (int r = 0; r < 8; r++)
        xg_base[r] = xg + (size_t)(b0 + r) * T_ * G_ + 2 * tid;

    for (int t = 0; t < T_; t++) {
        // phase A: gates = xg + h @ W_hh^T  (thread owns gate pair 2*tid, 2*tid+1 for 8 rows)
        ull acc[8];
#pragma unroll
        for (int r = 0; r < 8; r++)
            acc[r] = *(const ull*)(xg_base[r] + (size_t)t * G_);

#pragma unroll 2
        for (int k = 0; k < H_; k++) {
            ull w = WtP[k * 256 + tid];
            const longlong2* hk = (const longlong2*)hs_dup[k];
            longlong2 h01 = hk[0], h23 = hk[1], h45 = hk[2], h67 = hk[3];
            fma2(acc[0], w, (ull)h01.x, acc[0]);
            fma2(acc[1], w, (ull)h01.y, acc[1]);
            fma2(acc[2], w, (ull)h23.x, acc[2]);
            fma2(acc[3], w, (ull)h23.y, acc[3]);
            fma2(acc[4], w, (ull)h45.x, acc[4]);
            fma2(acc[5], w, (ull)h45.y, acc[5]);
            fma2(acc[6], w, (ull)h67.x, acc[6]);
            fma2(acc[7], w, (ull)h67.y, acc[7]);
        }
#pragma unroll
        for (int r = 0; r < 8; r++)
            *(ull*)&gs[r][2 * tid] = acc[r];
        __syncthreads();

        // phase B: activations + state update (gate order i, f, g, o)
#pragma unroll
        for (int q = 0; q < 2; q++) {
            int r = r_b[q], j = j_b[q];
            float2 gi = *(float2*)&gs[r][j];
            float2 gf = *(float2*)&gs[r][128 + j];
            float2 gg = *(float2*)&gs[r][256 + j];
            float2 go = *(float2*)&gs[r][384 + j];
            c_b[q].x = sigm_(gf.x) * c_b[q].x + sigm_(gi.x) * tanh_fast(gg.x);
            c_b[q].y = sigm_(gf.y) * c_b[q].y + sigm_(gi.y) * tanh_fast(gg.y);
            float h0v = sigm_(go.x) * tanh_fast(c_b[q].x);
            float h1v = sigm_(go.y) * tanh_fast(c_b[q].y);
            hs_dup[j][r]     = pack2(h0v, h0v);
            hs_dup[j + 1][r] = pack2(h1v, h1v);
            *(float2*)(hout + ((size_t)(b0 + r) * T_ + t) * H_ + j) = make_float2(h0v, h1v);
        }
        __syncthreads();
    }
}

// ---------------- projection head: ReLU(h @ Wp1^T + bp1) @ Wp2^T + bp2 ----------------
__global__ void __launch_bounds__(256) proj_kernel(const float* __restrict__ h,
                                                   const float* __restrict__ Wp1,
                                                   const float* __restrict__ bp1,
                                                   const float* __restrict__ Wp2,
                                                   const float* __restrict__ bp2,
                                                   float* __restrict__ out) {
    __shared__ float w1t[128][65];
    __shared__ float w2t[64][22];
    __shared__ float ps[32][64];
    __shared__ float b1s[64];
    __shared__ float b2s[22];
    int tid = threadIdx.x;

    for (int i = tid; i < P_ * H_; i += 256) { int jj = i >> 7, kk = i & 127; w1t[kk][jj] = Wp1[i]; }
    for (int i = tid; i < O_ * P_; i += 256) { int oo = i >> 6, kk = i & 63;  w2t[kk][oo] = Wp2[i]; }
    if (tid < P_) b1s[tid] = bp1[tid];
    if (tid < O_) b2s[tid] = bp2[tid];
    __syncthreads();

    size_t row0 = (size_t)blockIdx.x * 32;
    int jj = tid & 63;
    int rs = tid >> 6;
    float acc[8] = {};
    const float* hrow[8];
#pragma unroll
    for (int rr = 0; rr < 8; rr++) hrow[rr] = h + (row0 + (size_t)rs * 8 + rr) * H_;

    for (int k4 = 0; k4 < 32; k4++) {
        float4 hv[8];
#pragma unroll
        for (int rr = 0; rr < 8; rr++) hv[rr] = *(const float4*)(hrow[rr] + 4 * k4);
#pragma unroll
        for (int kk = 0; kk < 4; kk++) {
            float w = w1t[4 * k4 + kk][jj];
#pragma unroll
            for (int rr = 0; rr < 8; rr++) {
                float hvv = (&hv[rr].x)[kk];
                acc[rr] = fmaf(hvv, w, acc[rr]);
            }
        }
    }
#pragma unroll
    for (int rr = 0; rr < 8; rr++) {
        float v = acc[rr] + b1s[jj];
        ps[rs * 8 + rr][jj] = v > 0.f ? v : 0.f;
    }
    __syncthreads();

    for (int idx = tid; idx < 32 * O_; idx += 256) {
        int rr = idx / O_;
        int oo = idx - rr * O_;
        float s = b2s[oo];
#pragma unroll
        for (int k = 0; k < P_; k++) s = fmaf(ps[rr][k], w2t[k][oo], s);
        out[(row0 + rr) * O_ + oo] = s;
    }
}

// ---------------- launch ----------------
extern "C" void kernel_launch(void* const* d_in, const int* in_sizes, int n_in,
                              void* d_out, int out_size) {
    const float* x     = (const float*)d_in[0];
    const float* ln_g  = (const float*)d_in[1];
    const float* ln_b  = (const float*)d_in[2];
    const float* W_ih0 = (const float*)d_in[3];
    const float* W_hh0 = (const float*)d_in[4];
    const float* b0    = (const float*)d_in[5];
    const float* W_ih1 = (const float*)d_in[6];
    const float* W_hh1 = (const float*)d_in[7];
    const float* b1    = (const float*)d_in[8];
    const float* Wp1   = (const float*)d_in[9];
    const float* bp1   = (const float*)d_in[10];
    const float* Wp2   = (const float*)d_in[11];
    const float* bp2   = (const float*)d_in[12];
    float* out = (float*)d_out;

    float *xn, *xg, *h0, *wt0, *wt1;
    cudaGetSymbolAddress((void**)&xn,  g_xn);
    cudaGetSymbolAddress((void**)&xg,  g_xg);
    cudaGetSymbolAddress((void**)&h0,  g_h0);
    cudaGetSymbolAddress((void**)&wt0, g_Wt0);
    cudaGetSymbolAddress((void**)&wt1, g_Wt1);
    float* h1 = xn;   // reuse LN buffer for layer-1 h output

    transpose_whh_kernel<<<256, 256>>>(W_hh0, wt0);
    transpose_whh_kernel<<<256, 256>>>(W_hh1, wt1);

    ln_kernel<<<M_ / 8, 256>>>(x, ln_g, ln_b, xn);

    gemm2_kernel<D_><<<dim3(4, M_ / 128), 256>>>(xn, W_ih0, b0, xg);
    lstm8_kernel<<<B_ / 8, 256>>>(xg, wt0, h0);

    gemm2_kernel<H_><<<dim3(4, M_ / 128), 256>>>(h0, W_ih1, b1, xg);
    lstm8_kernel<<<B_ / 8, 256>>>(xg, wt1, h1);

    proj_kernel<<<M_ / 32, 256>>>(h1, Wp1, bp1, Wp2, bp2, out);
}

// round 7
// speedup vs baseline: 1.8643x; 1.8643x over previous
#include <cuda_runtime.h>
#include <cuda_bf16.h>
#include <stdint.h>
#include <math.h>

#define B_ 1024
#define T_ 250
#define D_ 158
#define H_ 128
#define G_ 512          // 4*H
#define M_ (B_*T_)      // 256000 rows
#define P_ 64
#define O_ 22

typedef unsigned long long ull;

// ---------------- scratch (device globals: the sanctioned alloc-free path) ----------------
__device__ float g_xn[(size_t)M_ * D_];   // LN output; later reused as layer-1 h output
__device__ float g_xg[(size_t)M_ * G_];   // precomputed input gates for current layer
__device__ float g_h0[(size_t)M_ * H_];   // layer-0 h sequence

// ---------------- f32x2 packed-FMA helpers ----------------
__device__ __forceinline__ void fma2(ull& d, ull a, ull b, ull c) {
    asm("fma.rn.f32x2 %0, %1, %2, %3;" : "=l"(d) : "l"(a), "l"(b), "l"(c));
}
__device__ __forceinline__ ull pack2(float a, float b) {
    ull r; asm("mov.b64 %0, {%1,%2};" : "=l"(r) : "f"(a), "f"(b)); return r;
}
__device__ __forceinline__ float2 upk2(ull v) {
    float2 r; asm("mov.b64 {%0,%1}, %2;" : "=f"(r.x), "=f"(r.y) : "l"(v)); return r;
}
__device__ __forceinline__ uint32_t s2u(const void* p) {
    return (uint32_t)__cvta_generic_to_shared(p);
}
__device__ __forceinline__ void st_remote_u64(uint32_t laddr, uint32_t peer, ull v) {
    uint32_t r;
    asm volatile("mapa.shared::cluster.u32 %0, %1, %2;" : "=r"(r) : "r"(laddr), "r"(peer));
    asm volatile("st.shared::cluster.b64 [%0], %1;" :: "r"(r), "l"(v) : "memory");
}

// ---------------- activation helpers (exact fp32 path, rel_err ~1e-6) ----------------
__device__ __forceinline__ float sigm_(float x) {
    return 1.f / (1.f + __expf(-x));
}
__device__ __forceinline__ float tanh_fast(float x) {
    float a = fabsf(x);
    float e = __expf(a + a);
    float t = 1.f - 2.f / (e + 1.f);
    return copysignf(t, x);
}

// ---------------- LayerNorm over last dim (158) ----------------
__global__ void __launch_bounds__(256) ln_kernel(const float* __restrict__ x,
                                                 const float* __restrict__ gamma,
                                                 const float* __restrict__ beta,
                                                 float* __restrict__ xn) {
    int row  = blockIdx.x * 8 + (threadIdx.x >> 5);
    int lane = threadIdx.x & 31;
    const float* xr = x + (size_t)row * D_;
    float v[5];
    float s = 0.f, s2 = 0.f;
#pragma unroll
    for (int i = 0; i < 5; i++) {
        int k = lane + 32 * i;
        v[i] = (k < D_) ? xr[k] : 0.f;
        s += v[i];
        s2 = fmaf(v[i], v[i], s2);
    }
#pragma unroll
    for (int o = 16; o; o >>= 1) {
        s  += __shfl_xor_sync(0xffffffffu, s, o);
        s2 += __shfl_xor_sync(0xffffffffu, s2, o);
    }
    float mu  = s * (1.f / D_);
    float var = s2 * (1.f / D_) - mu * mu;
    float inv = rsqrtf(var + 1e-5f);
    float* xo = xn + (size_t)row * D_;
#pragma unroll
    for (int i = 0; i < 5; i++) {
        int k = lane + 32 * i;
        if (k < D_) xo[k] = (v[i] - mu) * inv * gamma[k] + beta[k];
    }
}

// ---------------- FFMA2 GEMM: C[M,512] = A[M,K] * W[512,K]^T + bias ----------------
// BM=128, BN=128, BK=16, 256 threads, 8x8 microtile, A pre-duplicated for f32x2.
template <int K>
__global__ void __launch_bounds__(256, 2) gemm2_kernel(const float* __restrict__ A,
                                                       const float* __restrict__ W,
                                                       const float* __restrict__ bias,
                                                       float* __restrict__ C) {
    __shared__ ull   As[2][16][128];   // (a,a) duplicated pairs: 32 KB
    __shared__ float Bs[2][16][128];   // 16 KB
    constexpr int NT = (K + 15) / 16;

    int tid = threadIdx.x;
    int row = tid >> 1;                // 0..127
    int kb  = (tid & 1) * 8;           // 0 or 8
    int m0 = blockIdx.y * 128, n0 = blockIdx.x * 128;
    int tx = tid & 15, ty = tid >> 4;

    const float* Arow = A + (size_t)(m0 + row) * K;
    const float* Wrow = W + (size_t)(n0 + row) * K;

    ull acc[8][4];
#pragma unroll
    for (int i = 0; i < 8; i++)
#pragma unroll
        for (int j = 0; j < 4; j++) acc[i][j] = 0ull;

    float ar[8], br[8];
#pragma unroll
    for (int j = 0; j < 8; j++) {
        int k = kb + j;
        ar[j] = (k < K) ? Arow[k] : 0.f;
        br[j] = (k < K) ? Wrow[k] : 0.f;
    }
#pragma unroll
    for (int j = 0; j < 8; j++) {
        As[0][kb + j][row] = pack2(ar[j], ar[j]);
        Bs[0][kb + j][row] = br[j];
    }
    __syncthreads();

    for (int tIdx = 0; tIdx < NT; tIdx++) {
        int cur = tIdx & 1, nxt = cur ^ 1;
        if (tIdx + 1 < NT) {
            int k0 = (tIdx + 1) * 16;
#pragma unroll
            for (int j = 0; j < 8; j++) {
                int k = k0 + kb + j;
                ar[j] = (k < K) ? Arow[k] : 0.f;
                br[j] = (k < K) ? Wrow[k] : 0.f;
            }
        }
#pragma unroll
        for (int kk = 0; kk < 16; kk++) {
            const longlong2* ap = (const longlong2*)&As[cur][kk][ty * 8];
            longlong2 a01 = ap[0], a23 = ap[1], a45 = ap[2], a67 = ap[3];
            const longlong2* bp = (const longlong2*)&Bs[cur][kk][tx * 8];
            longlong2 b03 = bp[0], b47 = bp[1];
            ull au[8] = {(ull)a01.x, (ull)a01.y, (ull)a23.x, (ull)a23.y,
                         (ull)a45.x, (ull)a45.y, (ull)a67.x, (ull)a67.y};
            ull bu[4] = {(ull)b03.x, (ull)b03.y, (ull)b47.x, (ull)b47.y};
#pragma unroll
            for (int i = 0; i < 8; i++)
#pragma unroll
                for (int j = 0; j < 4; j++)
                    fma2(acc[i][j], au[i], bu[j], acc[i][j]);
        }
        if (tIdx + 1 < NT) {
#pragma unroll
            for (int j = 0; j < 8; j++) {
                As[nxt][kb + j][row] = pack2(ar[j], ar[j]);
                Bs[nxt][kb + j][row] = br[j];
            }
        }
        __syncthreads();
    }

    float bb[8];
#pragma unroll
    for (int j = 0; j < 8; j++) bb[j] = bias[n0 + tx * 8 + j];
#pragma unroll
    for (int i = 0; i < 8; i++) {
        float2 p0 = upk2(acc[i][0]);
        float2 p1 = upk2(acc[i][1]);
        float2 p2 = upk2(acc[i][2]);
        float2 p3 = upk2(acc[i][3]);
        float4 v0 = make_float4(p0.x + bb[0], p0.y + bb[1], p1.x + bb[2], p1.y + bb[3]);
        float4 v1 = make_float4(p2.x + bb[4], p2.y + bb[5], p3.x + bb[6], p3.y + bb[7]);
        float* crow = C + (size_t)(m0 + ty * 8 + i) * G_ + n0 + tx * 8;
        *(float4*)(crow)     = v0;
        *(float4*)(crow + 4) = v1;
    }
}

// ---------------- clustered LSTM recurrence ----------------
// Cluster of 2 CTAs owns 16 batch rows for all 250 steps.
// CTA rank c holds W_hh columns for hidden units [64c,64c+64) (= gate indices
// {128q+64c+j}) in SMEM as FFMA2 pairs (128 KB). Per step: each CTA computes its
// 256 gates x 16 rows (FFMA2), updates its 64 hidden units, mirrors the new h
// into the peer's parity-double-buffered h array via DSMEM, cluster barrier.
// Dynamic smem layout (ull units):
//   ws  [128k][128 gate-pairs]           131072 B
//   hs  [2 parity][128 unit][18 rows pad] 36864 B
//   gs  [16 rows][256 local gates] f32    16384 B   -> total 184320 B
#define LSTM_SMEM_BYTES (131072 + 36864 + 16384)

__global__ void __launch_bounds__(256) __cluster_dims__(2, 1, 1)
lstm_cluster_kernel(const float* __restrict__ xg,
                    const float* __restrict__ Whh,    // [512][128] row-major
                    float* __restrict__ hout) {
    extern __shared__ ull sm[];
    ull*   ws  = sm;                          // 128*128 pairs
    ull*   hsb = sm + 128 * 128;              // [2][128][18]
    float* gs  = (float*)(sm + 128 * 128 + 2 * 128 * 18);   // [16][256]

    int tid = threadIdx.x;
    uint32_t crank;
    asm("mov.u32 %0, %%cluster_ctarank;" : "=r"(crank));
    int c = (int)crank;
    int b0 = (blockIdx.x >> 1) * 16;

    // fill Ws: ws[k*128+gp] = (Whh[g0][k], Whh[g0+1][k]), g0 = 128q + 64c + 2(gp&31)
    for (int idx = tid; idx < 128 * 128; idx += 256) {
        int k = idx >> 7, gp = idx & 127;
        int q = gp >> 5, jl = 2 * (gp & 31);
        int g0 = 128 * q + 64 * c + jl;
        ws[idx] = pack2(Whh[g0 * 128 + k], Whh[g0 * 128 + 128 + k]);
    }
    for (int i = tid; i < 2 * 128 * 18; i += 256) hsb[i] = 0ull;
    __syncthreads();
    asm volatile("barrier.cluster.arrive.aligned;" ::: "memory");
    asm volatile("barrier.cluster.wait.aligned;" ::: "memory");

    // phase-A mapping: gate-pairs {2m, 2m+1} (4 consecutive units in quarter q), rows rh*4..rh*4+3
    int m  = tid & 63;
    int rh = tid >> 6;
    int q  = m >> 4;
    int jb = (4 * m) & 63;                 // local unit base (0..60)
    int gbase = 128 * q + 64 * c + jb;     // global gate base (4 consecutive)
    int gsoff = q * 64 + jb;               // local gs offset

    // phase-B mapping: warp w handles rows w and w+8, lane l handles local units 2l,2l+1
    int wB = tid >> 5;
    int l  = tid & 31;
    float2 cst[2] = {{0.f, 0.f}, {0.f, 0.f}};

    uint32_t hs_u32 = s2u(hsb);
    const float* xgp[4];
#pragma unroll
    for (int r = 0; r < 4; r++)
        xgp[r] = xg + (size_t)(b0 + rh * 4 + r) * T_ * G_ + gbase;

    // prefetch xg for t=0
    ulonglong2 pref[4];
#pragma unroll
    for (int r = 0; r < 4; r++) pref[r] = *(const ulonglong2*)(xgp[r]);

    for (int t = 0; t < T_; t++) {
        int par = t & 1;
        ull acc[4][2];
#pragma unroll
        for (int r = 0; r < 4; r++) { acc[r][0] = pref[r].x; acc[r][1] = pref[r].y; }
        // prefetch next step's xg (hidden behind the k-loop)
        int tn = (t + 1 < T_) ? (t + 1) : t;
#pragma unroll
        for (int r = 0; r < 4; r++)
            pref[r] = *(const ulonglong2*)(xgp[r] + (size_t)tn * G_);

        const ull* hpar = hsb + par * (128 * 18) + rh * 4;
        const ull* wsp  = ws + 2 * m;
#pragma unroll 4
        for (int k = 0; k < H_; k++) {
            ulonglong2 w2 = *(const ulonglong2*)(wsp + k * 128);
            ulonglong2 ha = *(const ulonglong2*)(hpar + k * 18);
            ulonglong2 hb = *(const ulonglong2*)(hpar + k * 18 + 2);
            fma2(acc[0][0], (ull)w2.x, (ull)ha.x, acc[0][0]);
            fma2(acc[0][1], (ull)w2.y, (ull)ha.x, acc[0][1]);
            fma2(acc[1][0], (ull)w2.x, (ull)ha.y, acc[1][0]);
            fma2(acc[1][1], (ull)w2.y, (ull)ha.y, acc[1][1]);
            fma2(acc[2][0], (ull)w2.x, (ull)hb.x, acc[2][0]);
            fma2(acc[2][1], (ull)w2.y, (ull)hb.x, acc[2][1]);
            fma2(acc[3][0], (ull)w2.x, (ull)hb.y, acc[3][0]);
            fma2(acc[3][1], (ull)w2.y, (ull)hb.y, acc[3][1]);
        }
#pragma unroll
        for (int r = 0; r < 4; r++) {
            int row = rh * 4 + r;
            *(ulonglong2*)&gs[row * 256 + gsoff] =
                make_ulonglong2((long long)acc[r][0], (long long)acc[r][1]);
        }
        __syncthreads();

        ull* hnew = hsb + (par ^ 1) * (128 * 18);
        uint32_t hnew_u32 = hs_u32 + (uint32_t)((par ^ 1) * (128 * 18)) * 8u;
#pragma unroll
        for (int s = 0; s < 2; s++) {
            int row = wB + 8 * s;
            float2 gi = *(float2*)&gs[row * 256 + 2 * l];
            float2 gf = *(float2*)&gs[row * 256 + 64 + 2 * l];
            float2 gg = *(float2*)&gs[row * 256 + 128 + 2 * l];
            float2 go = *(float2*)&gs[row * 256 + 192 + 2 * l];
            float2 cc = cst[s];
            cc.x = sigm_(gf.x) * cc.x + sigm_(gi.x) * tanh_fast(gg.x);
            cc.y = sigm_(gf.y) * cc.y + sigm_(gi.y) * tanh_fast(gg.y);
            float h0v = sigm_(go.x) * tanh_fast(cc.x);
            float h1v = sigm_(go.y) * tanh_fast(cc.y);
            cst[s] = cc;
            int j = 64 * c + 2 * l;
            ull p0 = pack2(h0v, h0v), p1 = pack2(h1v, h1v);
            hnew[(size_t)j * 18 + row]       = p0;
            hnew[(size_t)(j + 1) * 18 + row] = p1;
            uint32_t a0 = hnew_u32 + (uint32_t)(j * 18 + row) * 8u;
            st_remote_u64(a0,            (uint32_t)(c ^ 1), p0);
            st_remote_u64(a0 + 18u * 8u, (uint32_t)(c ^ 1), p1);
            *(float2*)&hout[((size_t)(b0 + row) * T_ + t) * H_ + j] = make_float2(h0v, h1v);
        }
        asm volatile("barrier.cluster.arrive.aligned;" ::: "memory");
        asm volatile("barrier.cluster.wait.aligned;" ::: "memory");
    }
}

// ---------------- projection head: ReLU(h @ Wp1^T + bp1) @ Wp2^T + bp2 ----------------
__global__ void __launch_bounds__(256) proj_kernel(const float* __restrict__ h,
                                                   const float* __restrict__ Wp1,
                                                   const float* __restrict__ bp1,
                                                   const float* __restrict__ Wp2,
                                                   const float* __restrict__ bp2,
                                                   float* __restrict__ out) {
    __shared__ float w1t[128][65];
    __shared__ float w2t[64][22];
    __shared__ float ps[32][64];
    __shared__ float b1s[64];
    __shared__ float b2s[22];
    int tid = threadIdx.x;

    for (int i = tid; i < P_ * H_; i += 256) { int jj = i >> 7, kk = i & 127; w1t[kk][jj] = Wp1[i]; }
    for (int i = tid; i < O_ * P_; i += 256) { int oo = i >> 6, kk = i & 63;  w2t[kk][oo] = Wp2[i]; }
    if (tid < P_) b1s[tid] = bp1[tid];
    if (tid < O_) b2s[tid] = bp2[tid];
    __syncthreads();

    size_t row0 = (size_t)blockIdx.x * 32;
    int jj = tid & 63;
    int rs = tid >> 6;
    float acc[8] = {};
    const float* hrow[8];
#pragma unroll
    for (int rr = 0; rr < 8; rr++) hrow[rr] = h + (row0 + (size_t)rs * 8 + rr) * H_;

    for (int k4 = 0; k4 < 32; k4++) {
        float4 hv[8];
#pragma unroll
        for (int rr = 0; rr < 8; rr++) hv[rr] = *(const float4*)(hrow[rr] + 4 * k4);
#pragma unroll
        for (int kk = 0; kk < 4; kk++) {
            float w = w1t[4 * k4 + kk][jj];
#pragma unroll
            for (int rr = 0; rr < 8; rr++) {
                float hvv = (&hv[rr].x)[kk];
                acc[rr] = fmaf(hvv, w, acc[rr]);
            }
        }
    }
#pragma unroll
    for (int rr = 0; rr < 8; rr++) {
        float v = acc[rr] + b1s[jj];
        ps[rs * 8 + rr][jj] = v > 0.f ? v : 0.f;
    }
    __syncthreads();

    for (int idx = tid; idx < 32 * O_; idx += 256) {
        int rr = idx / O_;
        int oo = idx - rr * O_;
        float s = b2s[oo];
#pragma unroll
        for (int k = 0; k < P_; k++) s = fmaf(ps[rr][k], w2t[k][oo], s);
        out[(row0 + rr) * O_ + oo] = s;
    }
}

// ---------------- launch ----------------
extern "C" void kernel_launch(void* const* d_in, const int* in_sizes, int n_in,
                              void* d_out, int out_size) {
    const float* x     = (const float*)d_in[0];
    const float* ln_g  = (const float*)d_in[1];
    const float* ln_b  = (const float*)d_in[2];
    const float* W_ih0 = (const float*)d_in[3];
    const float* W_hh0 = (const float*)d_in[4];
    const float* b0    = (const float*)d_in[5];
    const float* W_ih1 = (const float*)d_in[6];
    const float* W_hh1 = (const float*)d_in[7];
    const float* b1    = (const float*)d_in[8];
    const float* Wp1   = (const float*)d_in[9];
    const float* bp1   = (const float*)d_in[10];
    const float* Wp2   = (const float*)d_in[11];
    const float* bp2   = (const float*)d_in[12];
    float* out = (float*)d_out;

    float *xn, *xg, *h0;
    cudaGetSymbolAddress((void**)&xn, g_xn);
    cudaGetSymbolAddress((void**)&xg, g_xg);
    cudaGetSymbolAddress((void**)&h0, g_h0);
    float* h1 = xn;   // reuse LN buffer for layer-1 h output

    cudaFuncSetAttribute(lstm_cluster_kernel,
                         cudaFuncAttributeMaxDynamicSharedMemorySize, LSTM_SMEM_BYTES);

    ln_kernel<<<M_ / 8, 256>>>(x, ln_g, ln_b, xn);

    gemm2_kernel<D_><<<dim3(4, M_ / 128), 256>>>(xn, W_ih0, b0, xg);
    lstm_cluster_kernel<<<128, 256, LSTM_SMEM_BYTES>>>(xg, W_hh0, h0);

    gemm2_kernel<H_><<<dim3(4, M_ / 128), 256>>>(h0, W_ih1, b1, xg);
    lstm_cluster_kernel<<<128, 256, LSTM_SMEM_BYTES>>>(xg, W_hh1, h1);

    proj_kernel<<<M_ / 32, 256>>>(h1, Wp1, bp1, Wp2, bp2, out);
}